// round 10
// baseline (speedup 1.0000x reference)
#include <cuda_runtime.h>
#include <cuda_bf16.h>
#include <cuda_fp16.h>
#include <cstdint>
#include <cstddef>

#define NN 100000
#define EE 1600000
#define NBLK 98  // ceil(NN/1024)
#define LDS_S 40 // smem row stride (bf16 elems)

// ---------------- scratch (device globals) ---------------------------------
__device__ __half g_xl16[(size_t)NN * 128];  // x @ W_l1 (fp16, gather payload)
__device__ float  g_xr[(size_t)NN * 128];    // x @ W_r1 (fp32)
__device__ __half g_hl16[(size_t)NN * 64];   // h @ W_l2 (fp16, gather payload)
__device__ float  g_hr[(size_t)NN * 64];     // h @ W_r2 (fp32)
__device__ int   g_deg[NN];
__device__ int   g_rowptr[NN + 1];
__device__ int   g_cursor[NN];
__device__ int   g_csr[EE];
__device__ int   g_blksum[128];
__device__ int   g_is64;
__device__ __nv_bfloat16 g_ahi[(size_t)NN * 128];  // h split (layer-2 A operand)
__device__ __nv_bfloat16 g_alo[(size_t)NN * 128];
__device__ __nv_bfloat16 g_w1T_hi[256 * 128];
__device__ __nv_bfloat16 g_w1T_lo[256 * 128];
__device__ __nv_bfloat16 g_w2T_hi[128 * 128];
__device__ __nv_bfloat16 g_w2T_lo[128 * 128];

// ---------------- dtype detection (parallel, 256 threads) -------------------
// int32 ids fit in 17 bits; int64 reads of an int32 buffer give values >= 2^32
// for almost all samples. All 256 in [0, NN) => buffer is int64.
__global__ void detect_kernel(const void* __restrict__ ei_raw) {
    const long long* e64 = (const long long*)ei_raw;
    int i = threadIdx.x;
    long long v = e64[i];
    int ok = (v >= 0 && v < NN) ? 1 : 0;
    unsigned m = __ballot_sync(0xffffffffu, ok);
    __shared__ int warpok[8];
    if ((i & 31) == 0) warpok[i >> 5] = (m == 0xffffffffu) ? 1 : 0;
    __syncthreads();
    if (i == 0) {
        int all = 1;
#pragma unroll
        for (int w = 0; w < 8; w++) all &= warpok[w];
        g_is64 = all;
    }
}

__global__ void zero_deg_kernel() {
    int i = blockIdx.x * blockDim.x + threadIdx.x;
    if (i < NN) g_deg[i] = 0;
}

__global__ void count_kernel(const void* __restrict__ ei_raw) {
    int i = blockIdx.x * blockDim.x + threadIdx.x;
    int stride = gridDim.x * blockDim.x;
    if (g_is64) {
        const long long* e64 = (const long long*)ei_raw;
        for (int e = i; e < EE; e += stride) {
            int d = (int)e64[(size_t)EE + e];
            d = min(max(d, 0), NN - 1);
            atomicAdd(&g_deg[d], 1);
        }
    } else {
        const int* e32 = (const int*)ei_raw;
        for (int e = i; e < EE; e += stride) {
            int d = e32[EE + e];
            d = min(max(d, 0), NN - 1);
            atomicAdd(&g_deg[d], 1);
        }
    }
}

__global__ void scan1_kernel() {
    __shared__ int sm[1024];
    int gi = blockIdx.x * 1024 + threadIdx.x;
    int v = (gi < NN) ? g_deg[gi] : 0;
    sm[threadIdx.x] = v;
    __syncthreads();
    for (int off = 1; off < 1024; off <<= 1) {
        int t = (threadIdx.x >= off) ? sm[threadIdx.x - off] : 0;
        __syncthreads();
        sm[threadIdx.x] += t;
        __syncthreads();
    }
    if (gi < NN) g_rowptr[gi] = sm[threadIdx.x] - v;
    if (threadIdx.x == 1023) g_blksum[blockIdx.x] = sm[1023];
}

// parallel exclusive scan over the 98 block sums (one 128-thread block)
__global__ void scan2_kernel() {
    __shared__ int sm[128];
    int i = threadIdx.x;
    int v = (i < NBLK) ? g_blksum[i] : 0;
    sm[i] = v;
    __syncthreads();
    for (int off = 1; off < 128; off <<= 1) {
        int t = (i >= off) ? sm[i - off] : 0;
        __syncthreads();
        sm[i] += t;
        __syncthreads();
    }
    if (i < NBLK) g_blksum[i] = sm[i] - v;  // exclusive
}

__global__ void scan3_kernel() {
    int gi = blockIdx.x * 1024 + threadIdx.x;
    if (gi < NN) {
        int v = g_rowptr[gi] + g_blksum[gi >> 10];
        g_rowptr[gi] = v;
        g_cursor[gi] = v;
    }
    if (gi == 0) g_rowptr[NN] = EE;
}

__global__ void bin_kernel(const void* __restrict__ ei_raw) {
    int i = blockIdx.x * blockDim.x + threadIdx.x;
    int stride = gridDim.x * blockDim.x;
    if (g_is64) {
        const long long* e64 = (const long long*)ei_raw;
        for (int e = i; e < EE; e += stride) {
            int s = (int)e64[e];
            int d = (int)e64[(size_t)EE + e];
            s = min(max(s, 0), NN - 1);
            d = min(max(d, 0), NN - 1);
            int pos = atomicAdd(&g_cursor[d], 1);
            g_csr[pos] = s;
        }
    } else {
        const int* e32 = (const int*)ei_raw;
        for (int e = i; e < EE; e += stride) {
            int s = e32[e];
            int d = e32[EE + e];
            s = min(max(s, 0), NN - 1);
            d = min(max(d, 0), NN - 1);
            int pos = atomicAdd(&g_cursor[d], 1);
            g_csr[pos] = s;
        }
    }
}

// ---------------- split helpers --------------------------------------------
__device__ __forceinline__ void split2(float a, float b,
                                       __nv_bfloat162& hi, __nv_bfloat162& lo) {
    __nv_bfloat16 ha = __float2bfloat16_rn(a);
    __nv_bfloat16 hb = __float2bfloat16_rn(b);
    __nv_bfloat16 la = __float2bfloat16_rn(a - __bfloat162float(ha));
    __nv_bfloat16 lb = __float2bfloat16_rn(b - __bfloat162float(hb));
    hi = __nv_bfloat162(ha, hb);
    lo = __nv_bfloat162(la, lb);
}

// ---------------- weights -> transposed bf16 hi/lo --------------------------
__global__ void wconvert_kernel(const float* __restrict__ Wl1,
                                const float* __restrict__ Wr1,
                                const float* __restrict__ Wl2,
                                const float* __restrict__ Wr2) {
    int i = blockIdx.x * blockDim.x + threadIdx.x;
    int stride = gridDim.x * blockDim.x;
    for (int idx = i; idx < 256 * 128; idx += stride) {
        int n = idx >> 7, k = idx & 127;
        float v = (n < 128) ? Wl1[k * 128 + n] : Wr1[k * 128 + (n - 128)];
        __nv_bfloat16 h = __float2bfloat16_rn(v);
        g_w1T_hi[idx] = h;
        g_w1T_lo[idx] = __float2bfloat16_rn(v - __bfloat162float(h));
    }
    for (int idx = i; idx < 128 * 128; idx += stride) {
        int n = idx >> 7, k = idx & 127;
        float v = (n < 64) ? Wl2[k * 64 + n] : Wr2[k * 64 + (n - 64)];
        __nv_bfloat16 h = __float2bfloat16_rn(v);
        g_w2T_hi[idx] = h;
        g_w2T_lo[idx] = __float2bfloat16_rn(v - __bfloat162float(h));
    }
}

// ---------------- cp.async helpers ------------------------------------------
__device__ __forceinline__ void cp16(void* smem, const void* g, int szbytes) {
    uint32_t sa = (uint32_t)__cvta_generic_to_shared(smem);
    asm volatile("cp.async.ca.shared.global [%0], [%1], 16, %2;"
                 :: "r"(sa), "l"(g), "r"(szbytes));
}
#define CP_COMMIT() asm volatile("cp.async.commit_group;")
#define CP_WAIT0()  asm volatile("cp.async.wait_group 0;")

// ---------------- bf16 split MMA (m16n8k16) ---------------------------------
__device__ __forceinline__ void mma16816(float* c, const uint32_t* a, const uint32_t* b) {
    asm volatile("mma.sync.aligned.m16n8k16.row.col.f32.bf16.bf16.f32 "
                 "{%0,%1,%2,%3}, {%4,%5,%6,%7}, {%8,%9}, {%0,%1,%2,%3};"
                 : "+f"(c[0]), "+f"(c[1]), "+f"(c[2]), "+f"(c[3])
                 : "r"(a[0]), "r"(a[1]), "r"(a[2]), "r"(a[3]),
                   "r"(b[0]), "r"(b[1]));
}

// ---------------- pipelined dual-weight GEMM --------------------------------
template <int MODE>
__global__ void __launch_bounds__(256)
mma_gemm_pipe(const float* __restrict__ Afp,
              const __nv_bfloat16* __restrict__ Ahi,
              const __nv_bfloat16* __restrict__ Alo,
              const __nv_bfloat16* __restrict__ WThi,
              const __nv_bfloat16* __restrict__ WTlo,
              __half* __restrict__ Chalf,
              float* __restrict__ Cfloat, int M) {
    extern __shared__ char smraw[];
    __nv_bfloat16* sA_hi = reinterpret_cast<__nv_bfloat16*>(smraw);
    __nv_bfloat16* sA_lo = sA_hi + 2 * 64 * LDS_S;
    __nv_bfloat16* sB_hi = sA_lo + 2 * 64 * LDS_S;
    __nv_bfloat16* sB_lo = sB_hi + 2 * 128 * LDS_S;

    const int tid = threadIdx.x;
    const int wid = tid >> 5;
    const int lane = tid & 31;
    const int g = lane >> 2;
    const int t = lane & 3;
    const int wm = wid & 1;
    const int wn = wid >> 1;
    const int row0 = blockIdx.x * 64;
    const int n0 = blockIdx.y * 128;

    const int ar = tid >> 2, aq = tid & 3;
    const int agr = row0 + ar;
    const bool aval = agr < M;
    const int agr_c = aval ? agr : (M - 1);

    float4 av0, av1;

    auto loadB = [&](int kc, int st) {
#pragma unroll
        for (int j = 0; j < 2; j++) {
            int idx = tid + j * 256;
            int n = idx >> 2, q = idx & 3;
            size_t gi = (size_t)(n0 + n) * 128 + kc * 32 + q * 8;
            int si = st * 128 * LDS_S + n * LDS_S + q * 8;
            cp16(sB_hi + si, WThi + gi, 16);
            cp16(sB_lo + si, WTlo + gi, 16);
        }
    };
    auto loadA_async = [&](int kc, int st) {
        size_t gi = (size_t)agr_c * 128 + kc * 32 + aq * 8;
        int si = st * 64 * LDS_S + ar * LDS_S + aq * 8;
        int sz = aval ? 16 : 0;
        cp16(sA_hi + si, Ahi + gi, sz);
        cp16(sA_lo + si, Alo + gi, sz);
    };
    auto ldgA = [&](int kc) {
        if (aval) {
            const float* p = Afp + (size_t)agr * 128 + kc * 32 + aq * 8;
            av0 = *reinterpret_cast<const float4*>(p);
            av1 = *reinterpret_cast<const float4*>(p + 4);
        } else {
            av0 = make_float4(0.f, 0.f, 0.f, 0.f);
            av1 = make_float4(0.f, 0.f, 0.f, 0.f);
        }
    };
    auto stsA = [&](int st) {
        __nv_bfloat162 h0, l0, h1, l1, h2, l2, h3, l3;
        split2(av0.x, av0.y, h0, l0);
        split2(av0.z, av0.w, h1, l1);
        split2(av1.x, av1.y, h2, l2);
        split2(av1.z, av1.w, h3, l3);
        int si = st * 64 * LDS_S + ar * LDS_S + aq * 8;
        uint4 ph = make_uint4(*reinterpret_cast<uint32_t*>(&h0),
                              *reinterpret_cast<uint32_t*>(&h1),
                              *reinterpret_cast<uint32_t*>(&h2),
                              *reinterpret_cast<uint32_t*>(&h3));
        uint4 pl = make_uint4(*reinterpret_cast<uint32_t*>(&l0),
                              *reinterpret_cast<uint32_t*>(&l1),
                              *reinterpret_cast<uint32_t*>(&l2),
                              *reinterpret_cast<uint32_t*>(&l3));
        *reinterpret_cast<uint4*>(sA_hi + si) = ph;
        *reinterpret_cast<uint4*>(sA_lo + si) = pl;
    };

    float acc[2][4][4];
#pragma unroll
    for (int mt = 0; mt < 2; mt++)
#pragma unroll
        for (int nt = 0; nt < 4; nt++)
#pragma unroll
            for (int c = 0; c < 4; c++) acc[mt][nt][c] = 0.f;

    auto compute = [&](int st) {
        const __nv_bfloat16* pAh = sA_hi + st * 64 * LDS_S;
        const __nv_bfloat16* pAl = sA_lo + st * 64 * LDS_S;
        const __nv_bfloat16* pBh = sB_hi + st * 128 * LDS_S;
        const __nv_bfloat16* pBl = sB_lo + st * 128 * LDS_S;
#pragma unroll
        for (int ks = 0; ks < 32; ks += 16) {
            uint32_t a[2][2][4];
#pragma unroll
            for (int mt = 0; mt < 2; mt++) {
                int base = (wm * 32 + mt * 16 + g) * LDS_S + ks + t * 2;
                a[mt][0][0] = *reinterpret_cast<const uint32_t*>(pAh + base);
                a[mt][0][1] = *reinterpret_cast<const uint32_t*>(pAh + base + 8 * LDS_S);
                a[mt][0][2] = *reinterpret_cast<const uint32_t*>(pAh + base + 8);
                a[mt][0][3] = *reinterpret_cast<const uint32_t*>(pAh + base + 8 * LDS_S + 8);
                a[mt][1][0] = *reinterpret_cast<const uint32_t*>(pAl + base);
                a[mt][1][1] = *reinterpret_cast<const uint32_t*>(pAl + base + 8 * LDS_S);
                a[mt][1][2] = *reinterpret_cast<const uint32_t*>(pAl + base + 8);
                a[mt][1][3] = *reinterpret_cast<const uint32_t*>(pAl + base + 8 * LDS_S + 8);
            }
            uint32_t b[4][2][2];
#pragma unroll
            for (int nt = 0; nt < 4; nt++) {
                int base = (wn * 32 + nt * 8 + g) * LDS_S + ks + t * 2;
                b[nt][0][0] = *reinterpret_cast<const uint32_t*>(pBh + base);
                b[nt][0][1] = *reinterpret_cast<const uint32_t*>(pBh + base + 8);
                b[nt][1][0] = *reinterpret_cast<const uint32_t*>(pBl + base);
                b[nt][1][1] = *reinterpret_cast<const uint32_t*>(pBl + base + 8);
            }
#pragma unroll
            for (int mt = 0; mt < 2; mt++)
#pragma unroll
                for (int nt = 0; nt < 4; nt++) {
                    mma16816(acc[mt][nt], a[mt][0], b[nt][0]);
                    mma16816(acc[mt][nt], a[mt][0], b[nt][1]);
                    mma16816(acc[mt][nt], a[mt][1], b[nt][0]);
                }
        }
    };

    if (MODE == 1) {
        loadB(0, 0); CP_COMMIT();
        ldgA(0);
        CP_WAIT0();
        stsA(0);
        __syncthreads();
#pragma unroll
        for (int kc = 0; kc < 4; kc++) {
            if (kc < 3) { loadB(kc + 1, (kc + 1) & 1); CP_COMMIT(); ldgA(kc + 1); }
            compute(kc & 1);
            if (kc < 3) { CP_WAIT0(); stsA((kc + 1) & 1); __syncthreads(); }
        }
    } else {
        loadA_async(0, 0); loadB(0, 0); CP_COMMIT();
        CP_WAIT0();
        __syncthreads();
#pragma unroll
        for (int kc = 0; kc < 4; kc++) {
            if (kc < 3) { loadA_async(kc + 1, (kc + 1) & 1); loadB(kc + 1, (kc + 1) & 1); CP_COMMIT(); }
            compute(kc & 1);
            if (kc < 3) { CP_WAIT0(); __syncthreads(); }
        }
    }

    // -------- epilogue --------
#pragma unroll
    for (int mt = 0; mt < 2; mt++) {
        int row = row0 + wm * 32 + mt * 16 + g;
#pragma unroll
        for (int nt = 0; nt < 4; nt++) {
            int col = wn * 32 + nt * 8 + t * 2;
#pragma unroll
            for (int half_ : {0, 1}) {
                int r = row + half_ * 8;
                if (r >= M) continue;
                float c0 = acc[mt][nt][half_ * 2 + 0];
                float c1 = acc[mt][nt][half_ * 2 + 1];
                if (MODE == 1) {
                    if (blockIdx.y == 0) {
                        __half2 hv = __floats2half2_rn(c0, c1);
                        *reinterpret_cast<__half2*>(Chalf + (size_t)r * 128 + col) = hv;
                    } else {
                        *reinterpret_cast<float2*>(Cfloat + (size_t)r * 128 + col) =
                            make_float2(c0, c1);
                    }
                } else {
                    if (col < 64) {
                        __half2 hv = __floats2half2_rn(c0, c1);
                        *reinterpret_cast<__half2*>(Chalf + (size_t)r * 64 + col) = hv;
                    } else {
                        *reinterpret_cast<float2*>(Cfloat + (size_t)r * 64 + (col - 64)) =
                            make_float2(c0, c1);
                    }
                }
            }
        }
    }
}

// ---------------- gather layer 1: warp/node, fp16 payload -------------------
__global__ void __launch_bounds__(256) gather1_kernel(const float* __restrict__ b1) {
    int w = (blockIdx.x * 256 + threadIdx.x) >> 5;
    if (w >= NN) return;
    int lane = threadIdx.x & 31;
    int beg = g_rowptr[w], end = g_rowptr[w + 1];
    float4 a0 = make_float4(0.f, 0.f, 0.f, 0.f);
    float4 a1 = make_float4(0.f, 0.f, 0.f, 0.f);
    float4 a2 = make_float4(0.f, 0.f, 0.f, 0.f);
    float4 a3 = make_float4(0.f, 0.f, 0.f, 0.f);
    const int off = lane * 4;
    int j = beg;
    for (; j + 4 <= end; j += 4) {
        int s0 = g_csr[j], s1 = g_csr[j + 1], s2 = g_csr[j + 2], s3 = g_csr[j + 3];
        uint2 u0 = *reinterpret_cast<const uint2*>(g_xl16 + (size_t)s0 * 128 + off);
        uint2 u1 = *reinterpret_cast<const uint2*>(g_xl16 + (size_t)s1 * 128 + off);
        uint2 u2 = *reinterpret_cast<const uint2*>(g_xl16 + (size_t)s2 * 128 + off);
        uint2 u3 = *reinterpret_cast<const uint2*>(g_xl16 + (size_t)s3 * 128 + off);
        float2 f;
        f = __half22float2(*reinterpret_cast<__half2*>(&u0.x)); a0.x += f.x; a0.y += f.y;
        f = __half22float2(*reinterpret_cast<__half2*>(&u0.y)); a0.z += f.x; a0.w += f.y;
        f = __half22float2(*reinterpret_cast<__half2*>(&u1.x)); a1.x += f.x; a1.y += f.y;
        f = __half22float2(*reinterpret_cast<__half2*>(&u1.y)); a1.z += f.x; a1.w += f.y;
        f = __half22float2(*reinterpret_cast<__half2*>(&u2.x)); a2.x += f.x; a2.y += f.y;
        f = __half22float2(*reinterpret_cast<__half2*>(&u2.y)); a2.z += f.x; a2.w += f.y;
        f = __half22float2(*reinterpret_cast<__half2*>(&u3.x)); a3.x += f.x; a3.y += f.y;
        f = __half22float2(*reinterpret_cast<__half2*>(&u3.y)); a3.z += f.x; a3.w += f.y;
    }
    for (; j < end; j++) {
        int s0 = g_csr[j];
        uint2 u0 = *reinterpret_cast<const uint2*>(g_xl16 + (size_t)s0 * 128 + off);
        float2 f;
        f = __half22float2(*reinterpret_cast<__half2*>(&u0.x)); a0.x += f.x; a0.y += f.y;
        f = __half22float2(*reinterpret_cast<__half2*>(&u0.y)); a0.z += f.x; a0.w += f.y;
    }
    float inv = 1.0f / fmaxf((float)(end - beg), 1.0f);
    float4 r = *reinterpret_cast<const float4*>(g_xr + (size_t)w * 128 + off);
    float4 bb = *reinterpret_cast<const float4*>(b1 + off);
    float h0 = fmaxf((a0.x + a1.x + a2.x + a3.x) * inv + bb.x + r.x, 0.f);
    float h1 = fmaxf((a0.y + a1.y + a2.y + a3.y) * inv + bb.y + r.y, 0.f);
    float h2 = fmaxf((a0.z + a1.z + a2.z + a3.z) * inv + bb.z + r.z, 0.f);
    float h3 = fmaxf((a0.w + a1.w + a2.w + a3.w) * inv + bb.w + r.w, 0.f);
    __nv_bfloat162 hi0, lo0, hi1, lo1;
    split2(h0, h1, hi0, lo0);
    split2(h2, h3, hi1, lo1);
    size_t o = (size_t)w * 128 + off;
    uint2 ph = make_uint2(*reinterpret_cast<uint32_t*>(&hi0),
                          *reinterpret_cast<uint32_t*>(&hi1));
    uint2 pl = make_uint2(*reinterpret_cast<uint32_t*>(&lo0),
                          *reinterpret_cast<uint32_t*>(&lo1));
    *reinterpret_cast<uint2*>(g_ahi + o) = ph;
    *reinterpret_cast<uint2*>(g_alo + o) = pl;
}

// ---------------- gather layer 2: warp/node, fp16 payload -------------------
__global__ void __launch_bounds__(256) gather2_kernel(const float* __restrict__ b2,
                                                      float* __restrict__ out) {
    int w = (blockIdx.x * 256 + threadIdx.x) >> 5;
    if (w >= NN) return;
    int lane = threadIdx.x & 31;
    int beg = g_rowptr[w], end = g_rowptr[w + 1];
    float2 a0 = make_float2(0.f, 0.f);
    float2 a1 = make_float2(0.f, 0.f);
    float2 a2 = make_float2(0.f, 0.f);
    float2 a3 = make_float2(0.f, 0.f);
    const int off = lane * 2;
    int j = beg;
    for (; j + 4 <= end; j += 4) {
        int s0 = g_csr[j], s1 = g_csr[j + 1], s2 = g_csr[j + 2], s3 = g_csr[j + 3];
        uint32_t u0 = *reinterpret_cast<const uint32_t*>(g_hl16 + (size_t)s0 * 64 + off);
        uint32_t u1 = *reinterpret_cast<const uint32_t*>(g_hl16 + (size_t)s1 * 64 + off);
        uint32_t u2 = *reinterpret_cast<const uint32_t*>(g_hl16 + (size_t)s2 * 64 + off);
        uint32_t u3 = *reinterpret_cast<const uint32_t*>(g_hl16 + (size_t)s3 * 64 + off);
        float2 f;
        f = __half22float2(*reinterpret_cast<__half2*>(&u0)); a0.x += f.x; a0.y += f.y;
        f = __half22float2(*reinterpret_cast<__half2*>(&u1)); a1.x += f.x; a1.y += f.y;
        f = __half22float2(*reinterpret_cast<__half2*>(&u2)); a2.x += f.x; a2.y += f.y;
        f = __half22float2(*reinterpret_cast<__half2*>(&u3)); a3.x += f.x; a3.y += f.y;
    }
    for (; j < end; j++) {
        int s0 = g_csr[j];
        uint32_t u0 = *reinterpret_cast<const uint32_t*>(g_hl16 + (size_t)s0 * 64 + off);
        float2 f = __half22float2(*reinterpret_cast<__half2*>(&u0));
        a0.x += f.x; a0.y += f.y;
    }
    float inv = 1.0f / fmaxf((float)(end - beg), 1.0f);
    float2 r = *reinterpret_cast<const float2*>(g_hr + (size_t)w * 64 + off);
    float2 bb = *reinterpret_cast<const float2*>(b2 + off);
    float2 o;
    o.x = (a0.x + a1.x + a2.x + a3.x) * inv + bb.x + r.x;
    o.y = (a0.y + a1.y + a2.y + a3.y) * inv + bb.y + r.y;
    *reinterpret_cast<float2*>(out + (size_t)w * 64 + off) = o;
}

// ---------------- launch ---------------------------------------------------
extern "C" void kernel_launch(void* const* d_in, const int* in_sizes, int n_in,
                              void* d_out, int out_size) {
    const float* x    = (const float*)d_in[0];
    const void*  ei   = d_in[1];
    const float* W_l1 = (const float*)d_in[2];
    const float* W_r1 = (const float*)d_in[3];
    const float* b1   = (const float*)d_in[4];
    const float* W_l2 = (const float*)d_in[5];
    const float* W_r2 = (const float*)d_in[6];
    const float* b2   = (const float*)d_in[7];
    float* out = (float*)d_out;

    const int GB = (NN + 63) / 64;
    const int GW = (NN * 32 + 255) / 256;
    const int SMEM = (2 * 64 * LDS_S + 2 * 64 * LDS_S +
                      2 * 128 * LDS_S + 2 * 128 * LDS_S) * 2;  // 61,440 B

    __nv_bfloat16 *w1hi, *w1lo, *w2hi, *w2lo, *ahi, *alo;
    __half *xl16, *hl16;
    float *xr, *hr;
    cudaGetSymbolAddress((void**)&w1hi, g_w1T_hi);
    cudaGetSymbolAddress((void**)&w1lo, g_w1T_lo);
    cudaGetSymbolAddress((void**)&w2hi, g_w2T_hi);
    cudaGetSymbolAddress((void**)&w2lo, g_w2T_lo);
    cudaGetSymbolAddress((void**)&ahi, g_ahi);
    cudaGetSymbolAddress((void**)&alo, g_alo);
    cudaGetSymbolAddress((void**)&xl16, g_xl16);
    cudaGetSymbolAddress((void**)&hl16, g_hl16);
    cudaGetSymbolAddress((void**)&xr, g_xr);
    cudaGetSymbolAddress((void**)&hr, g_hr);

    cudaFuncSetAttribute(mma_gemm_pipe<1>,
                         cudaFuncAttributeMaxDynamicSharedMemorySize, SMEM);
    cudaFuncSetAttribute(mma_gemm_pipe<2>,
                         cudaFuncAttributeMaxDynamicSharedMemorySize, SMEM);

    static cudaStream_t s2 = ([] {
        cudaStream_t s;
        cudaStreamCreateWithFlags(&s, cudaStreamNonBlocking);
        return s;
    })();
    static cudaEvent_t evFork = ([] {
        cudaEvent_t e;
        cudaEventCreateWithFlags(&e, cudaEventDisableTiming);
        return e;
    })();
    static cudaEvent_t evCsr = ([] {
        cudaEvent_t e;
        cudaEventCreateWithFlags(&e, cudaEventDisableTiming);
        return e;
    })();

    cudaEventRecord(evFork, 0);
    cudaStreamWaitEvent(s2, evFork, 0);

    wconvert_kernel<<<256, 256>>>(W_l1, W_r1, W_l2, W_r2);
    detect_kernel<<<1, 256, 0, s2>>>(ei);
    mma_gemm_pipe<1><<<dim3(GB, 2), 256, SMEM>>>(
        x, nullptr, nullptr, w1hi, w1lo, xl16, xr, NN);
    zero_deg_kernel<<<NBLK, 1024, 0, s2>>>();
    count_kernel<<<2048, 256, 0, s2>>>(ei);
    scan1_kernel<<<NBLK, 1024, 0, s2>>>();
    scan2_kernel<<<1, 128, 0, s2>>>();
    scan3_kernel<<<NBLK, 1024, 0, s2>>>();
    bin_kernel<<<2048, 256, 0, s2>>>(ei);
    cudaEventRecord(evCsr, s2);

    cudaStreamWaitEvent(0, evCsr, 0);
    gather1_kernel<<<GW, 256>>>(b1);
    mma_gemm_pipe<2><<<dim3(GB, 1), 256, SMEM>>>(
        nullptr, ahi, alo, w2hi, w2lo, hl16, hr, NN);
    gather2_kernel<<<GW, 256>>>(b2, out);
}

// round 12
// speedup vs baseline: 1.0555x; 1.0555x over previous
#include <cuda_runtime.h>
#include <cuda_bf16.h>
#include <cuda_fp16.h>
#include <cstdint>
#include <cstddef>

#define NN 100000
#define EE 1600000
#define NBLK 98  // ceil(NN/1024)
#define LDS_S 40 // smem row stride (2-byte elems)

// ---------------- scratch (device globals) ---------------------------------
__device__ __half g_xl16[(size_t)NN * 128];  // x @ W_l1 (fp16, gather payload)
__device__ float  g_xr[(size_t)NN * 128];    // x @ W_r1 (fp32)
__device__ __half g_hl16[(size_t)NN * 64];   // h @ W_l2 (fp16, gather payload)
__device__ float  g_hr[(size_t)NN * 64];     // h @ W_r2 (fp32)
__device__ int   g_deg[NN];
__device__ int   g_rowptr[NN + 1];
__device__ int   g_cursor[NN];
__device__ int   g_csr[EE];
__device__ int   g_blksum[128];
__device__ int   g_is64;
__device__ __nv_bfloat16 g_ahi[(size_t)NN * 128];  // h split (layer-2 A operand)
__device__ __nv_bfloat16 g_alo[(size_t)NN * 128];
__device__ __nv_bfloat16 g_w1T_hi[256 * 128];      // [n][k] (only rows 128..255 used)
__device__ __nv_bfloat16 g_w1T_lo[256 * 128];
__device__ __half        g_w1T_f16[128 * 128];     // [n][k] W_l1^T fp16 (1-pass path)
__device__ __nv_bfloat16 g_w2T_hi[128 * 128];
__device__ __nv_bfloat16 g_w2T_lo[128 * 128];

// ---------------- dtype detection (parallel) --------------------------------
__global__ void detect_kernel(const void* __restrict__ ei_raw) {
    const long long* e64 = (const long long*)ei_raw;
    int i = threadIdx.x;
    long long v = e64[i];
    int ok = (v >= 0 && v < NN) ? 1 : 0;
    unsigned m = __ballot_sync(0xffffffffu, ok);
    __shared__ int warpok[8];
    if ((i & 31) == 0) warpok[i >> 5] = (m == 0xffffffffu) ? 1 : 0;
    __syncthreads();
    if (i == 0) {
        int all = 1;
#pragma unroll
        for (int w = 0; w < 8; w++) all &= warpok[w];
        g_is64 = all;
    }
}

__global__ void zero_deg_kernel() {
    int i = blockIdx.x * blockDim.x + threadIdx.x;
    if (i < NN) g_deg[i] = 0;
}

__global__ void count_kernel(const void* __restrict__ ei_raw) {
    int i = blockIdx.x * blockDim.x + threadIdx.x;
    int stride = gridDim.x * blockDim.x;
    if (g_is64) {
        const long long* e64 = (const long long*)ei_raw;
        for (int e = i; e < EE; e += stride) {
            int d = (int)e64[(size_t)EE + e];
            d = min(max(d, 0), NN - 1);
            atomicAdd(&g_deg[d], 1);
        }
    } else {
        const int* e32 = (const int*)ei_raw;
        for (int e = i; e < EE; e += stride) {
            int d = e32[EE + e];
            d = min(max(d, 0), NN - 1);
            atomicAdd(&g_deg[d], 1);
        }
    }
}

__global__ void scan1_kernel() {
    __shared__ int sm[1024];
    int gi = blockIdx.x * 1024 + threadIdx.x;
    int v = (gi < NN) ? g_deg[gi] : 0;
    sm[threadIdx.x] = v;
    __syncthreads();
    for (int off = 1; off < 1024; off <<= 1) {
        int t = (threadIdx.x >= off) ? sm[threadIdx.x - off] : 0;
        __syncthreads();
        sm[threadIdx.x] += t;
        __syncthreads();
    }
    if (gi < NN) g_rowptr[gi] = sm[threadIdx.x] - v;
    if (threadIdx.x == 1023) g_blksum[blockIdx.x] = sm[1023];
}

__global__ void scan2_kernel() {
    __shared__ int sm[128];
    int i = threadIdx.x;
    int v = (i < NBLK) ? g_blksum[i] : 0;
    sm[i] = v;
    __syncthreads();
    for (int off = 1; off < 128; off <<= 1) {
        int t = (i >= off) ? sm[i - off] : 0;
        __syncthreads();
        sm[i] += t;
        __syncthreads();
    }
    if (i < NBLK) g_blksum[i] = sm[i] - v;
}

__global__ void scan3_kernel() {
    int gi = blockIdx.x * 1024 + threadIdx.x;
    if (gi < NN) {
        int v = g_rowptr[gi] + g_blksum[gi >> 10];
        g_rowptr[gi] = v;
        g_cursor[gi] = v;
    }
    if (gi == 0) g_rowptr[NN] = EE;
}

__global__ void bin_kernel(const void* __restrict__ ei_raw) {
    int i = blockIdx.x * blockDim.x + threadIdx.x;
    int stride = gridDim.x * blockDim.x;
    if (g_is64) {
        const long long* e64 = (const long long*)ei_raw;
        for (int e = i; e < EE; e += stride) {
            int s = (int)e64[e];
            int d = (int)e64[(size_t)EE + e];
            s = min(max(s, 0), NN - 1);
            d = min(max(d, 0), NN - 1);
            int pos = atomicAdd(&g_cursor[d], 1);
            g_csr[pos] = s;
        }
    } else {
        const int* e32 = (const int*)ei_raw;
        for (int e = i; e < EE; e += stride) {
            int s = e32[e];
            int d = e32[EE + e];
            s = min(max(s, 0), NN - 1);
            d = min(max(d, 0), NN - 1);
            int pos = atomicAdd(&g_cursor[d], 1);
            g_csr[pos] = s;
        }
    }
}

// ---------------- split helpers --------------------------------------------
__device__ __forceinline__ void split2(float a, float b,
                                       __nv_bfloat162& hi, __nv_bfloat162& lo) {
    __nv_bfloat16 ha = __float2bfloat16_rn(a);
    __nv_bfloat16 hb = __float2bfloat16_rn(b);
    __nv_bfloat16 la = __float2bfloat16_rn(a - __bfloat162float(ha));
    __nv_bfloat16 lb = __float2bfloat16_rn(b - __bfloat162float(hb));
    hi = __nv_bfloat162(ha, hb);
    lo = __nv_bfloat162(la, lb);
}

// ---------------- weights -> transposed bf16 hi/lo + fp16 -------------------
__global__ void wconvert_kernel(const float* __restrict__ Wl1,
                                const float* __restrict__ Wr1,
                                const float* __restrict__ Wl2,
                                const float* __restrict__ Wr2) {
    int i = blockIdx.x * blockDim.x + threadIdx.x;
    int stride = gridDim.x * blockDim.x;
    for (int idx = i; idx < 256 * 128; idx += stride) {
        int n = idx >> 7, k = idx & 127;
        float v = (n < 128) ? Wl1[k * 128 + n] : Wr1[k * 128 + (n - 128)];
        __nv_bfloat16 h = __float2bfloat16_rn(v);
        g_w1T_hi[idx] = h;
        g_w1T_lo[idx] = __float2bfloat16_rn(v - __bfloat162float(h));
        if (n < 128) g_w1T_f16[idx] = __float2half_rn(v);
    }
    for (int idx = i; idx < 128 * 128; idx += stride) {
        int n = idx >> 7, k = idx & 127;
        float v = (n < 64) ? Wl2[k * 64 + n] : Wr2[k * 64 + (n - 64)];
        __nv_bfloat16 h = __float2bfloat16_rn(v);
        g_w2T_hi[idx] = h;
        g_w2T_lo[idx] = __float2bfloat16_rn(v - __bfloat162float(h));
    }
}

// ---------------- cp.async helpers ------------------------------------------
__device__ __forceinline__ void cp16(void* smem, const void* g, int szbytes) {
    uint32_t sa = (uint32_t)__cvta_generic_to_shared(smem);
    asm volatile("cp.async.ca.shared.global [%0], [%1], 16, %2;"
                 :: "r"(sa), "l"(g), "r"(szbytes));
}
#define CP_COMMIT() asm volatile("cp.async.commit_group;")
#define CP_WAIT0()  asm volatile("cp.async.wait_group 0;")

// ---------------- MMA (m16n8k16, bf16 and fp16) -----------------------------
__device__ __forceinline__ void mma16816(float* c, const uint32_t* a, const uint32_t* b) {
    asm volatile("mma.sync.aligned.m16n8k16.row.col.f32.bf16.bf16.f32 "
                 "{%0,%1,%2,%3}, {%4,%5,%6,%7}, {%8,%9}, {%0,%1,%2,%3};"
                 : "+f"(c[0]), "+f"(c[1]), "+f"(c[2]), "+f"(c[3])
                 : "r"(a[0]), "r"(a[1]), "r"(a[2]), "r"(a[3]),
                   "r"(b[0]), "r"(b[1]));
}
__device__ __forceinline__ void mma16816h(float* c, const uint32_t* a, const uint32_t* b) {
    asm volatile("mma.sync.aligned.m16n8k16.row.col.f32.f16.f16.f32 "
                 "{%0,%1,%2,%3}, {%4,%5,%6,%7}, {%8,%9}, {%0,%1,%2,%3};"
                 : "+f"(c[0]), "+f"(c[1]), "+f"(c[2]), "+f"(c[3])
                 : "r"(a[0]), "r"(a[1]), "r"(a[2]), "r"(a[3]),
                   "r"(b[0]), "r"(b[1]));
}

// ---------------- pipelined dual-weight GEMM --------------------------------
// Block tile 64(m) x 128(n), K=128 in 4 chunks of 32, 2-stage cp.async pipe.
// MODE 1, blockIdx.y==0: xl = x @ W_l1, 1-pass fp16 (output is fp16 anyway).
// MODE 1, blockIdx.y==1: xr = x @ W_r1, 3-pass bf16 split (fp32 output).
// MODE 2: [hl16 | hr] from pre-split h, 3-pass bf16.
template <int MODE>
__global__ void __launch_bounds__(256)
mma_gemm_pipe(const float* __restrict__ Afp,
              const __nv_bfloat16* __restrict__ Ahi,
              const __nv_bfloat16* __restrict__ Alo,
              const __nv_bfloat16* __restrict__ WThi,
              const __nv_bfloat16* __restrict__ WTlo,
              const __half* __restrict__ Wf16,
              __half* __restrict__ Chalf,
              float* __restrict__ Cfloat, int M) {
    extern __shared__ char smraw[];
    __nv_bfloat16* sA_hi = reinterpret_cast<__nv_bfloat16*>(smraw);
    __nv_bfloat16* sA_lo = sA_hi + 2 * 64 * LDS_S;
    __nv_bfloat16* sB_hi = sA_lo + 2 * 64 * LDS_S;
    __nv_bfloat16* sB_lo = sB_hi + 2 * 128 * LDS_S;

    const int tid = threadIdx.x;
    const int wid = tid >> 5;
    const int lane = tid & 31;
    const int g = lane >> 2;
    const int t = lane & 3;
    const int wm = wid & 1;
    const int wn = wid >> 1;
    const int row0 = blockIdx.x * 64;
    const int n0 = blockIdx.y * 128;

    const int ar = tid >> 2, aq = tid & 3;
    const int agr = row0 + ar;
    const bool aval = agr < M;

    float4 av0, av1;

    auto ldgA = [&](int kc) {
        if (aval) {
            const float* p = Afp + (size_t)agr * 128 + kc * 32 + aq * 8;
            av0 = *reinterpret_cast<const float4*>(p);
            av1 = *reinterpret_cast<const float4*>(p + 4);
        } else {
            av0 = make_float4(0.f, 0.f, 0.f, 0.f);
            av1 = make_float4(0.f, 0.f, 0.f, 0.f);
        }
    };

    float acc[2][4][4];
#pragma unroll
    for (int mt = 0; mt < 2; mt++)
#pragma unroll
        for (int nt = 0; nt < 4; nt++)
#pragma unroll
            for (int c = 0; c < 4; c++) acc[mt][nt][c] = 0.f;

    if (MODE == 1 && blockIdx.y == 0) {
        // ---------- 1-pass fp16 path: xl = x @ W_l1 ----------
        auto loadB16 = [&](int kc, int st) {
#pragma unroll
            for (int j = 0; j < 2; j++) {
                int idx = tid + j * 256;
                int n = idx >> 2, q = idx & 3;
                size_t gi = (size_t)n * 128 + kc * 32 + q * 8;
                int si = st * 128 * LDS_S + n * LDS_S + q * 8;
                cp16(sB_hi + si, Wf16 + gi, 16);
            }
        };
        auto stsA16 = [&](int st) {
            __half2 h0 = __floats2half2_rn(av0.x, av0.y);
            __half2 h1 = __floats2half2_rn(av0.z, av0.w);
            __half2 h2 = __floats2half2_rn(av1.x, av1.y);
            __half2 h3 = __floats2half2_rn(av1.z, av1.w);
            int si = st * 64 * LDS_S + ar * LDS_S + aq * 8;
            uint4 p = make_uint4(*reinterpret_cast<uint32_t*>(&h0),
                                 *reinterpret_cast<uint32_t*>(&h1),
                                 *reinterpret_cast<uint32_t*>(&h2),
                                 *reinterpret_cast<uint32_t*>(&h3));
            *reinterpret_cast<uint4*>(sA_hi + si) = p;
        };
        auto compute16 = [&](int st) {
            const __nv_bfloat16* pA = sA_hi + st * 64 * LDS_S;
            const __nv_bfloat16* pB = sB_hi + st * 128 * LDS_S;
#pragma unroll
            for (int ks = 0; ks < 32; ks += 16) {
                uint32_t a[2][4];
#pragma unroll
                for (int mt = 0; mt < 2; mt++) {
                    int base = (wm * 32 + mt * 16 + g) * LDS_S + ks + t * 2;
                    a[mt][0] = *reinterpret_cast<const uint32_t*>(pA + base);
                    a[mt][1] = *reinterpret_cast<const uint32_t*>(pA + base + 8 * LDS_S);
                    a[mt][2] = *reinterpret_cast<const uint32_t*>(pA + base + 8);
                    a[mt][3] = *reinterpret_cast<const uint32_t*>(pA + base + 8 * LDS_S + 8);
                }
                uint32_t b[4][2];
#pragma unroll
                for (int nt = 0; nt < 4; nt++) {
                    int base = (wn * 32 + nt * 8 + g) * LDS_S + ks + t * 2;
                    b[nt][0] = *reinterpret_cast<const uint32_t*>(pB + base);
                    b[nt][1] = *reinterpret_cast<const uint32_t*>(pB + base + 8);
                }
#pragma unroll
                for (int mt = 0; mt < 2; mt++)
#pragma unroll
                    for (int nt = 0; nt < 4; nt++)
                        mma16816h(acc[mt][nt], a[mt], b[nt]);
            }
        };

        loadB16(0, 0); CP_COMMIT();
        ldgA(0);
        CP_WAIT0();
        stsA16(0);
        __syncthreads();
#pragma unroll
        for (int kc = 0; kc < 4; kc++) {
            if (kc < 3) { loadB16(kc + 1, (kc + 1) & 1); CP_COMMIT(); ldgA(kc + 1); }
            compute16(kc & 1);
            if (kc < 3) { CP_WAIT0(); stsA16((kc + 1) & 1); __syncthreads(); }
        }
    } else {
        // ---------- 3-pass bf16 split path ----------
        auto loadB = [&](int kc, int st) {
#pragma unroll
            for (int j = 0; j < 2; j++) {
                int idx = tid + j * 256;
                int n = idx >> 2, q = idx & 3;
                size_t gi = (size_t)(n0 + n) * 128 + kc * 32 + q * 8;
                int si = st * 128 * LDS_S + n * LDS_S + q * 8;
                cp16(sB_hi + si, WThi + gi, 16);
                cp16(sB_lo + si, WTlo + gi, 16);
            }
        };
        auto loadA_async = [&](int kc, int st) {
            int rg = aval ? agr : (M - 1);
            size_t gi = (size_t)rg * 128 + kc * 32 + aq * 8;
            int si = st * 64 * LDS_S + ar * LDS_S + aq * 8;
            int sz = aval ? 16 : 0;
            cp16(sA_hi + si, Ahi + gi, sz);
            cp16(sA_lo + si, Alo + gi, sz);
        };
        auto stsA = [&](int st) {
            __nv_bfloat162 h0, l0, h1, l1, h2, l2, h3, l3;
            split2(av0.x, av0.y, h0, l0);
            split2(av0.z, av0.w, h1, l1);
            split2(av1.x, av1.y, h2, l2);
            split2(av1.z, av1.w, h3, l3);
            int si = st * 64 * LDS_S + ar * LDS_S + aq * 8;
            uint4 ph = make_uint4(*reinterpret_cast<uint32_t*>(&h0),
                                  *reinterpret_cast<uint32_t*>(&h1),
                                  *reinterpret_cast<uint32_t*>(&h2),
                                  *reinterpret_cast<uint32_t*>(&h3));
            uint4 pl = make_uint4(*reinterpret_cast<uint32_t*>(&l0),
                                  *reinterpret_cast<uint32_t*>(&l1),
                                  *reinterpret_cast<uint32_t*>(&l2),
                                  *reinterpret_cast<uint32_t*>(&l3));
            *reinterpret_cast<uint4*>(sA_hi + si) = ph;
            *reinterpret_cast<uint4*>(sA_lo + si) = pl;
        };
        auto compute = [&](int st) {
            const __nv_bfloat16* pAh = sA_hi + st * 64 * LDS_S;
            const __nv_bfloat16* pAl = sA_lo + st * 64 * LDS_S;
            const __nv_bfloat16* pBh = sB_hi + st * 128 * LDS_S;
            const __nv_bfloat16* pBl = sB_lo + st * 128 * LDS_S;
#pragma unroll
            for (int ks = 0; ks < 32; ks += 16) {
                uint32_t a[2][2][4];
#pragma unroll
                for (int mt = 0; mt < 2; mt++) {
                    int base = (wm * 32 + mt * 16 + g) * LDS_S + ks + t * 2;
                    a[mt][0][0] = *reinterpret_cast<const uint32_t*>(pAh + base);
                    a[mt][0][1] = *reinterpret_cast<const uint32_t*>(pAh + base + 8 * LDS_S);
                    a[mt][0][2] = *reinterpret_cast<const uint32_t*>(pAh + base + 8);
                    a[mt][0][3] = *reinterpret_cast<const uint32_t*>(pAh + base + 8 * LDS_S + 8);
                    a[mt][1][0] = *reinterpret_cast<const uint32_t*>(pAl + base);
                    a[mt][1][1] = *reinterpret_cast<const uint32_t*>(pAl + base + 8 * LDS_S);
                    a[mt][1][2] = *reinterpret_cast<const uint32_t*>(pAl + base + 8);
                    a[mt][1][3] = *reinterpret_cast<const uint32_t*>(pAl + base + 8 * LDS_S + 8);
                }
                uint32_t b[4][2][2];
#pragma unroll
                for (int nt = 0; nt < 4; nt++) {
                    int base = (wn * 32 + nt * 8 + g) * LDS_S + ks + t * 2;
                    b[nt][0][0] = *reinterpret_cast<const uint32_t*>(pBh + base);
                    b[nt][0][1] = *reinterpret_cast<const uint32_t*>(pBh + base + 8);
                    b[nt][1][0] = *reinterpret_cast<const uint32_t*>(pBl + base);
                    b[nt][1][1] = *reinterpret_cast<const uint32_t*>(pBl + base + 8);
                }
#pragma unroll
                for (int mt = 0; mt < 2; mt++)
#pragma unroll
                    for (int nt = 0; nt < 4; nt++) {
                        mma16816(acc[mt][nt], a[mt][0], b[nt][0]);
                        mma16816(acc[mt][nt], a[mt][0], b[nt][1]);
                        mma16816(acc[mt][nt], a[mt][1], b[nt][0]);
                    }
            }
        };

        if (MODE == 1) {
            loadB(0, 0); CP_COMMIT();
            ldgA(0);
            CP_WAIT0();
            stsA(0);
            __syncthreads();
#pragma unroll
            for (int kc = 0; kc < 4; kc++) {
                if (kc < 3) { loadB(kc + 1, (kc + 1) & 1); CP_COMMIT(); ldgA(kc + 1); }
                compute(kc & 1);
                if (kc < 3) { CP_WAIT0(); stsA((kc + 1) & 1); __syncthreads(); }
            }
        } else {
            loadA_async(0, 0); loadB(0, 0); CP_COMMIT();
            CP_WAIT0();
            __syncthreads();
#pragma unroll
            for (int kc = 0; kc < 4; kc++) {
                if (kc < 3) { loadA_async(kc + 1, (kc + 1) & 1); loadB(kc + 1, (kc + 1) & 1); CP_COMMIT(); }
                compute(kc & 1);
                if (kc < 3) { CP_WAIT0(); __syncthreads(); }
            }
        }
    }

    // -------- epilogue --------
#pragma unroll
    for (int mt = 0; mt < 2; mt++) {
        int row = row0 + wm * 32 + mt * 16 + g;
#pragma unroll
        for (int nt = 0; nt < 4; nt++) {
            int col = wn * 32 + nt * 8 + t * 2;
#pragma unroll
            for (int half_ : {0, 1}) {
                int r = row + half_ * 8;
                if (r >= M) continue;
                float c0 = acc[mt][nt][half_ * 2 + 0];
                float c1 = acc[mt][nt][half_ * 2 + 1];
                if (MODE == 1) {
                    if (blockIdx.y == 0) {
                        __half2 hv = __floats2half2_rn(c0, c1);
                        *reinterpret_cast<__half2*>(Chalf + (size_t)r * 128 + col) = hv;
                    } else {
                        *reinterpret_cast<float2*>(Cfloat + (size_t)r * 128 + col) =
                            make_float2(c0, c1);
                    }
                } else {
                    if (col < 64) {
                        __half2 hv = __floats2half2_rn(c0, c1);
                        *reinterpret_cast<__half2*>(Chalf + (size_t)r * 64 + col) = hv;
                    } else {
                        *reinterpret_cast<float2*>(Cfloat + (size_t)r * 64 + (col - 64)) =
                            make_float2(c0, c1);
                    }
                }
            }
        }
    }
}

// ---------------- gather layer 1: warp/node, fp16 payload -------------------
__global__ void __launch_bounds__(256) gather1_kernel(const float* __restrict__ b1) {
    int w = (blockIdx.x * 256 + threadIdx.x) >> 5;
    if (w >= NN) return;
    int lane = threadIdx.x & 31;
    int beg = g_rowptr[w], end = g_rowptr[w + 1];
    float4 a0 = make_float4(0.f, 0.f, 0.f, 0.f);
    float4 a1 = make_float4(0.f, 0.f, 0.f, 0.f);
    float4 a2 = make_float4(0.f, 0.f, 0.f, 0.f);
    float4 a3 = make_float4(0.f, 0.f, 0.f, 0.f);
    const int off = lane * 4;
    int j = beg;
    for (; j + 4 <= end; j += 4) {
        int s0 = g_csr[j], s1 = g_csr[j + 1], s2 = g_csr[j + 2], s3 = g_csr[j + 3];
        uint2 u0 = *reinterpret_cast<const uint2*>(g_xl16 + (size_t)s0 * 128 + off);
        uint2 u1 = *reinterpret_cast<const uint2*>(g_xl16 + (size_t)s1 * 128 + off);
        uint2 u2 = *reinterpret_cast<const uint2*>(g_xl16 + (size_t)s2 * 128 + off);
        uint2 u3 = *reinterpret_cast<const uint2*>(g_xl16 + (size_t)s3 * 128 + off);
        float2 f;
        f = __half22float2(*reinterpret_cast<__half2*>(&u0.x)); a0.x += f.x; a0.y += f.y;
        f = __half22float2(*reinterpret_cast<__half2*>(&u0.y)); a0.z += f.x; a0.w += f.y;
        f = __half22float2(*reinterpret_cast<__half2*>(&u1.x)); a1.x += f.x; a1.y += f.y;
        f = __half22float2(*reinterpret_cast<__half2*>(&u1.y)); a1.z += f.x; a1.w += f.y;
        f = __half22float2(*reinterpret_cast<__half2*>(&u2.x)); a2.x += f.x; a2.y += f.y;
        f = __half22float2(*reinterpret_cast<__half2*>(&u2.y)); a2.z += f.x; a2.w += f.y;
        f = __half22float2(*reinterpret_cast<__half2*>(&u3.x)); a3.x += f.x; a3.y += f.y;
        f = __half22float2(*reinterpret_cast<__half2*>(&u3.y)); a3.z += f.x; a3.w += f.y;
    }
    for (; j < end; j++) {
        int s0 = g_csr[j];
        uint2 u0 = *reinterpret_cast<const uint2*>(g_xl16 + (size_t)s0 * 128 + off);
        float2 f;
        f = __half22float2(*reinterpret_cast<__half2*>(&u0.x)); a0.x += f.x; a0.y += f.y;
        f = __half22float2(*reinterpret_cast<__half2*>(&u0.y)); a0.z += f.x; a0.w += f.y;
    }
    float inv = 1.0f / fmaxf((float)(end - beg), 1.0f);
    float4 r = *reinterpret_cast<const float4*>(g_xr + (size_t)w * 128 + off);
    float4 bb = *reinterpret_cast<const float4*>(b1 + off);
    float h0 = fmaxf((a0.x + a1.x + a2.x + a3.x) * inv + bb.x + r.x, 0.f);
    float h1 = fmaxf((a0.y + a1.y + a2.y + a3.y) * inv + bb.y + r.y, 0.f);
    float h2 = fmaxf((a0.z + a1.z + a2.z + a3.z) * inv + bb.z + r.z, 0.f);
    float h3 = fmaxf((a0.w + a1.w + a2.w + a3.w) * inv + bb.w + r.w, 0.f);
    __nv_bfloat162 hi0, lo0, hi1, lo1;
    split2(h0, h1, hi0, lo0);
    split2(h2, h3, hi1, lo1);
    size_t o = (size_t)w * 128 + off;
    uint2 ph = make_uint2(*reinterpret_cast<uint32_t*>(&hi0),
                          *reinterpret_cast<uint32_t*>(&hi1));
    uint2 pl = make_uint2(*reinterpret_cast<uint32_t*>(&lo0),
                          *reinterpret_cast<uint32_t*>(&lo1));
    *reinterpret_cast<uint2*>(g_ahi + o) = ph;
    *reinterpret_cast<uint2*>(g_alo + o) = pl;
}

// ---------------- gather layer 2: warp/node, fp16 payload -------------------
__global__ void __launch_bounds__(256) gather2_kernel(const float* __restrict__ b2,
                                                      float* __restrict__ out) {
    int w = (blockIdx.x * 256 + threadIdx.x) >> 5;
    if (w >= NN) return;
    int lane = threadIdx.x & 31;
    int beg = g_rowptr[w], end = g_rowptr[w + 1];
    float2 a0 = make_float2(0.f, 0.f);
    float2 a1 = make_float2(0.f, 0.f);
    float2 a2 = make_float2(0.f, 0.f);
    float2 a3 = make_float2(0.f, 0.f);
    const int off = lane * 2;
    int j = beg;
    for (; j + 4 <= end; j += 4) {
        int s0 = g_csr[j], s1 = g_csr[j + 1], s2 = g_csr[j + 2], s3 = g_csr[j + 3];
        uint32_t u0 = *reinterpret_cast<const uint32_t*>(g_hl16 + (size_t)s0 * 64 + off);
        uint32_t u1 = *reinterpret_cast<const uint32_t*>(g_hl16 + (size_t)s1 * 64 + off);
        uint32_t u2 = *reinterpret_cast<const uint32_t*>(g_hl16 + (size_t)s2 * 64 + off);
        uint32_t u3 = *reinterpret_cast<const uint32_t*>(g_hl16 + (size_t)s3 * 64 + off);
        float2 f;
        f = __half22float2(*reinterpret_cast<__half2*>(&u0)); a0.x += f.x; a0.y += f.y;
        f = __half22float2(*reinterpret_cast<__half2*>(&u1)); a1.x += f.x; a1.y += f.y;
        f = __half22float2(*reinterpret_cast<__half2*>(&u2)); a2.x += f.x; a2.y += f.y;
        f = __half22float2(*reinterpret_cast<__half2*>(&u3)); a3.x += f.x; a3.y += f.y;
    }
    for (; j < end; j++) {
        int s0 = g_csr[j];
        uint32_t u0 = *reinterpret_cast<const uint32_t*>(g_hl16 + (size_t)s0 * 64 + off);
        float2 f = __half22float2(*reinterpret_cast<__half2*>(&u0));
        a0.x += f.x; a0.y += f.y;
    }
    float inv = 1.0f / fmaxf((float)(end - beg), 1.0f);
    float2 r = *reinterpret_cast<const float2*>(g_hr + (size_t)w * 64 + off);
    float2 bb = *reinterpret_cast<const float2*>(b2 + off);
    float2 o;
    o.x = (a0.x + a1.x + a2.x + a3.x) * inv + bb.x + r.x;
    o.y = (a0.y + a1.y + a2.y + a3.y) * inv + bb.y + r.y;
    *reinterpret_cast<float2*>(out + (size_t)w * 64 + off) = o;
}

// ---------------- launch ---------------------------------------------------
extern "C" void kernel_launch(void* const* d_in, const int* in_sizes, int n_in,
                              void* d_out, int out_size) {
    const float* x    = (const float*)d_in[0];
    const void*  ei   = d_in[1];
    const float* W_l1 = (const float*)d_in[2];
    const float* W_r1 = (const float*)d_in[3];
    const float* b1   = (const float*)d_in[4];
    const float* W_l2 = (const float*)d_in[5];
    const float* W_r2 = (const float*)d_in[6];
    const float* b2   = (const float*)d_in[7];
    float* out = (float*)d_out;

    const int GB = (NN + 63) / 64;
    const int GW = (NN * 32 + 255) / 256;
    const int SMEM = (2 * 64 * LDS_S + 2 * 64 * LDS_S +
                      2 * 128 * LDS_S + 2 * 128 * LDS_S) * 2;  // 61,440 B

    __nv_bfloat16 *w1hi, *w1lo, *w2hi, *w2lo, *ahi, *alo;
    __half *xl16, *hl16, *w1f16;
    float *xr, *hr;
    cudaGetSymbolAddress((void**)&w1hi, g_w1T_hi);
    cudaGetSymbolAddress((void**)&w1lo, g_w1T_lo);
    cudaGetSymbolAddress((void**)&w2hi, g_w2T_hi);
    cudaGetSymbolAddress((void**)&w2lo, g_w2T_lo);
    cudaGetSymbolAddress((void**)&w1f16, g_w1T_f16);
    cudaGetSymbolAddress((void**)&ahi, g_ahi);
    cudaGetSymbolAddress((void**)&alo, g_alo);
    cudaGetSymbolAddress((void**)&xl16, g_xl16);
    cudaGetSymbolAddress((void**)&hl16, g_hl16);
    cudaGetSymbolAddress((void**)&xr, g_xr);
    cudaGetSymbolAddress((void**)&hr, g_hr);

    cudaFuncSetAttribute(mma_gemm_pipe<1>,
                         cudaFuncAttributeMaxDynamicSharedMemorySize, SMEM);
    cudaFuncSetAttribute(mma_gemm_pipe<2>,
                         cudaFuncAttributeMaxDynamicSharedMemorySize, SMEM);

    static cudaStream_t s2 = ([] {
        cudaStream_t s;
        cudaStreamCreateWithFlags(&s, cudaStreamNonBlocking);
        return s;
    })();
    static cudaEvent_t evFork = ([] {
        cudaEvent_t e;
        cudaEventCreateWithFlags(&e, cudaEventDisableTiming);
        return e;
    })();
    static cudaEvent_t evCsr = ([] {
        cudaEvent_t e;
        cudaEventCreateWithFlags(&e, cudaEventDisableTiming);
        return e;
    })();

    cudaEventRecord(evFork, 0);
    cudaStreamWaitEvent(s2, evFork, 0);

    wconvert_kernel<<<256, 256>>>(W_l1, W_r1, W_l2, W_r2);   // #1
    detect_kernel<<<1, 256, 0, s2>>>(ei);                     // #2
    zero_deg_kernel<<<NBLK, 1024, 0, s2>>>();                 // #3
    mma_gemm_pipe<1><<<dim3(GB, 2), 256, SMEM>>>(             // #4 (profiled slot)
        x, nullptr, nullptr, w1hi, w1lo, w1f16, xl16, xr, NN);
    count_kernel<<<2048, 256, 0, s2>>>(ei);                   // #5
    scan1_kernel<<<NBLK, 1024, 0, s2>>>();
    scan2_kernel<<<1, 128, 0, s2>>>();
    scan3_kernel<<<NBLK, 1024, 0, s2>>>();
    bin_kernel<<<2048, 256, 0, s2>>>(ei);
    cudaEventRecord(evCsr, s2);

    cudaStreamWaitEvent(0, evCsr, 0);
    gather1_kernel<<<GW, 256>>>(b1);
    mma_gemm_pipe<2><<<dim3(GB, 1), 256, SMEM>>>(
        nullptr, ahi, alo, w2hi, w2lo, nullptr, hl16, hr, NN);
    gather2_kernel<<<GW, 256>>>(b2, out);
}